// round 14
// baseline (speedup 1.0000x reference)
#include <cuda_runtime.h>
#include <cuda_bf16.h>
#include <math.h>
#include <stdint.h>

#define BB 32
#define CCH 512
#define HWD 1024
#define PP 128
#define X_ELEMS 16777216L

__device__ float g_G[BB*CCH*CCH];
__device__ float g_G2[BB*CCH*CCH];
__device__ float g_Y[BB*PP*CCH];
__device__ float g_Z[BB*PP*CCH];
__device__ float g_Li[BB*PP*PP];
__device__ float g_M1[BB*PP*PP];
__device__ float g_P[4*BB*PP*PP];
__device__ float g_xbar[BB*CCH];
__device__ float g_raw[BB*24];
__device__ float g_ctx[BB*256];
__device__ float g_tg[BB*32];
__device__ float g_pw[BB*256];
__device__ float g_cw[BB*CCH];

__constant__ int c_ux[10] = {0,1,2,3,1,2,3,2,3,3};
__constant__ int c_uy[10] = {0,0,0,0,1,1,1,2,2,3};
__constant__ int c_li[6]  = {1,2,3,2,3,3};
__constant__ int c_lj[6]  = {0,0,0,1,1,2};

extern __shared__ float dynsm[];

__device__ __forceinline__ float geluf(float x){
    return 0.5f*x*(1.0f + erff(x*0.70710678118654752f));
}
__device__ __forceinline__ float sigmoidf(float x){ return 1.0f/(1.0f+expf(-x)); }
__device__ __forceinline__ uint32_t hashu(uint32_t x){
    x ^= x>>16; x *= 0x7feb352dU; x ^= x>>15; x *= 0x846ca68bU; x ^= x>>16; return x;
}
__device__ __forceinline__ float blockSum(float v, float* red, int nw){
    int tid = threadIdx.x;
    #pragma unroll
    for (int o=16;o>0;o>>=1) v += __shfl_down_sync(0xffffffffu, v, o);
    if ((tid&31)==0) red[tid>>5] = v;
    __syncthreads();
    float s = 0.f;
    for (int i=0;i<nw;i++) s += red[i];
    __syncthreads();
    return s;
}

// ================= tf32 tensor-core GEMM, cp.async 3-stage pipeline =========
// C[m][n] = alpha * sum_k A[m][k]*B[n][k]; both row-major, k contiguous.
// sym=0: grid (N/128, M/128, z), z = ks*32+b.  sym=1: grid (10,1,BB) upper tiles.
#define SROW 20
#define STG  (128*SROW)
#define GT_SMEM (3*2*STG*4)

__device__ __forceinline__ void cp16(uint32_t d, const float* s){
    asm volatile("cp.async.cg.shared.global [%0], [%1], 16;" :: "r"(d), "l"(s));
}

__global__ __launch_bounds__(256,2) void gemmT_k(const float* __restrict__ A,
    const float* __restrict__ B, float* __restrict__ C,
    int N,int K,int ldA,int ldB, long bA,long bB,long bC, float alpha, int sym)
{
    uint32_t* sm = reinterpret_cast<uint32_t*>(dynsm);
    uint32_t sbase = (uint32_t)__cvta_generic_to_shared(sm);
    int z = blockIdx.z, b = z & 31, ks = z >> 5;
    int bm, bn;
    if (sym){ bm = c_uy[blockIdx.x]*128; bn = c_ux[blockIdx.x]*128; }
    else    { bm = blockIdx.y*128; bn = blockIdx.x*128; }
    const float* Ab = A + (long)b*bA + (long)bm*ldA + (long)ks*K;
    const float* Bb = B + (long)b*bB + (long)bn*ldB + (long)ks*K;
    float* Cb = C + (long)z*bC;
    int tid = threadIdx.x, lane = tid&31, wid = tid>>5;
    int lrow = tid&127, lhalf = tid>>7;
    const float* Ald = Ab + (long)lrow*ldA + lhalf*8;
    const float* Bld = Bb + (long)lrow*ldB + lhalf*8;
    uint32_t dA = sbase + (uint32_t)(lrow*SROW + lhalf*8)*4u;
    uint32_t dB = dA + STG*4;
    int wm = (wid&1)*64, wn = (wid>>1)*32;
    int r = lane>>2, kq = lane&3;
    float acc[4][4][4];
    #pragma unroll
    for (int i=0;i<4;i++)
        #pragma unroll
        for (int j=0;j<4;j++){ acc[i][j][0]=0.f; acc[i][j][1]=0.f; acc[i][j][2]=0.f; acc[i][j][3]=0.f; }

    const int KT = K>>4;
    #pragma unroll
    for (int pf=0; pf<2; pf++){
        if (pf < KT){
            uint32_t off = (uint32_t)(pf*2*STG)*4u;
            cp16(dA+off, Ald+pf*16); cp16(dA+off+16, Ald+pf*16+4);
            cp16(dB+off, Bld+pf*16); cp16(dB+off+16, Bld+pf*16+4);
        }
        asm volatile("cp.async.commit_group;");
    }
    for (int kt=0; kt<KT; kt++){
        asm volatile("cp.async.wait_group 1;");
        __syncthreads();
        int s = kt % 3;
        const uint32_t* Asm = sm + s*2*STG;
        const uint32_t* Bsm = Asm + STG;
        // k-relabel: fragment slot kq <-> col c=kh*8+2kq ; slot kq+4 <-> col c+1
        #pragma unroll
        for (int kh=0; kh<2; kh++){
            int c = kh*8 + 2*kq;
            uint32_t af[4][4], bf[4][2];
            #pragma unroll
            for (int mt=0;mt<4;mt++){
                int m = wm+mt*16+r;
                uint2 lo = *reinterpret_cast<const uint2*>(&Asm[m*SROW+c]);
                uint2 hi = *reinterpret_cast<const uint2*>(&Asm[(m+8)*SROW+c]);
                af[mt][0]=lo.x; af[mt][1]=hi.x; af[mt][2]=lo.y; af[mt][3]=hi.y;
            }
            #pragma unroll
            for (int nt=0;nt<4;nt++){
                int n = wn+nt*8+r;
                uint2 bb = *reinterpret_cast<const uint2*>(&Bsm[n*SROW+c]);
                bf[nt][0]=bb.x; bf[nt][1]=bb.y;
            }
            #pragma unroll
            for (int mt=0;mt<4;mt++)
                #pragma unroll
                for (int nt=0;nt<4;nt++){
                    asm volatile(
                      "mma.sync.aligned.m16n8k8.row.col.f32.tf32.tf32.f32 "
                      "{%0,%1,%2,%3},{%4,%5,%6,%7},{%8,%9},{%0,%1,%2,%3};"
                      : "+f"(acc[mt][nt][0]),"+f"(acc[mt][nt][1]),
                        "+f"(acc[mt][nt][2]),"+f"(acc[mt][nt][3])
                      : "r"(af[mt][0]),"r"(af[mt][1]),"r"(af[mt][2]),"r"(af[mt][3]),
                        "r"(bf[nt][0]),"r"(bf[nt][1]));
                }
        }
        int pf = kt+2;
        if (pf < KT){
            uint32_t off = (uint32_t)((pf%3)*2*STG)*4u;
            cp16(dA+off, Ald+pf*16); cp16(dA+off+16, Ald+pf*16+4);
            cp16(dB+off, Bld+pf*16); cp16(dB+off+16, Bld+pf*16+4);
        }
        asm volatile("cp.async.commit_group;");
    }
    #pragma unroll
    for (int mt=0;mt<4;mt++){
        int row0 = bm+wm+mt*16+r;
        #pragma unroll
        for (int nt=0;nt<4;nt++){
            int col = bn+wn+nt*8+2*kq;
            float2 v0; v0.x = alpha*acc[mt][nt][0]; v0.y = alpha*acc[mt][nt][1];
            float2 v1; v1.x = alpha*acc[mt][nt][2]; v1.y = alpha*acc[mt][nt][3];
            *reinterpret_cast<float2*>(&Cb[(long)row0*N + col]) = v0;
            *reinterpret_cast<float2*>(&Cb[(long)(row0+8)*N + col]) = v1;
        }
    }
}

// ---- mirror lower tiles from upper tiles (symmetric 512x512 per batch) ----
__global__ void mirror_k(float* __restrict__ G){
    float* s = dynsm;   // 128*129
    int ti = c_li[blockIdx.x], tj = c_lj[blockIdx.x];
    int b = blockIdx.z, tid = threadIdx.x;
    float* Gb = G + (long)b*CCH*CCH;
    const float* src = Gb + (long)(tj*128)*CCH + ti*128;   // upper tile (rows tj, cols ti)
    float* dst = Gb + (long)(ti*128)*CCH + tj*128;         // lower tile
    for (int idx=tid; idx<16384; idx+=256){
        int r=idx>>7, c=idx&127;
        s[r*129+c] = src[(long)r*CCH + c];
    }
    __syncthreads();
    for (int idx=tid; idx<16384; idx+=256){
        int r=idx>>7, c=idx&127;
        dst[(long)r*CCH + c] = s[c*129+r];
    }
}

// ========== 128x64-tile tf32 GEMM (M fixed = 128): fills the chip ==========
#define ASTG (128*SROW)
#define BSTG (64*SROW)
#define STG64 (ASTG+BSTG)
#define GT64_SMEM (3*STG64*4)

__global__ __launch_bounds__(256,2) void gemmT64_k(const float* __restrict__ A,
    const float* __restrict__ B, float* __restrict__ C,
    int N,int K,int ldA,int ldB, long bA,long bB,long bC, float alpha)
{
    uint32_t* sm = reinterpret_cast<uint32_t*>(dynsm);
    uint32_t sbase = (uint32_t)__cvta_generic_to_shared(sm);
    int b = blockIdx.z;
    int bn = blockIdx.x*64;
    const float* Ab = A + (long)b*bA;
    const float* Bb = B + (long)b*bB + (long)bn*ldB;
    float* Cb = C + (long)b*bC;
    int tid = threadIdx.x, lane = tid&31, wid = tid>>5;
    int lrow = tid&127, lhalf = tid>>7;
    const float* Ald = Ab + (long)lrow*ldA + lhalf*8;
    uint32_t dA = sbase + (uint32_t)(lrow*SROW + lhalf*8)*4u;
    int brow = tid&63, bhalf = (tid>>6)&1;
    const float* Bld = Bb + (long)brow*ldB + bhalf*8;
    uint32_t dB = sbase + (uint32_t)(ASTG + brow*SROW + bhalf*8)*4u;
    bool bload = (tid < 128);
    int wm = (wid&3)*32, wn = (wid>>2)*32;
    int r = lane>>2, kq = lane&3;
    float acc[2][4][4];
    #pragma unroll
    for (int i=0;i<2;i++)
        #pragma unroll
        for (int j=0;j<4;j++){ acc[i][j][0]=0.f; acc[i][j][1]=0.f; acc[i][j][2]=0.f; acc[i][j][3]=0.f; }

    const int KT = K>>4;
    #pragma unroll
    for (int pf=0; pf<2; pf++){
        if (pf < KT){
            uint32_t off = (uint32_t)(pf*STG64)*4u;
            cp16(dA+off, Ald+pf*16); cp16(dA+off+16, Ald+pf*16+4);
            if (bload){ cp16(dB+off, Bld+pf*16); cp16(dB+off+16, Bld+pf*16+4); }
        }
        asm volatile("cp.async.commit_group;");
    }
    for (int kt=0; kt<KT; kt++){
        asm volatile("cp.async.wait_group 1;");
        __syncthreads();
        const uint32_t* Asm = sm + (kt%3)*STG64;
        const uint32_t* Bsm = Asm + ASTG;
        #pragma unroll
        for (int kh=0; kh<2; kh++){
            int c = kh*8 + 2*kq;
            uint32_t af[2][4], bf[4][2];
            #pragma unroll
            for (int mt=0;mt<2;mt++){
                int m = wm+mt*16+r;
                uint2 lo = *reinterpret_cast<const uint2*>(&Asm[m*SROW+c]);
                uint2 hi = *reinterpret_cast<const uint2*>(&Asm[(m+8)*SROW+c]);
                af[mt][0]=lo.x; af[mt][1]=hi.x; af[mt][2]=lo.y; af[mt][3]=hi.y;
            }
            #pragma unroll
            for (int nt=0;nt<4;nt++){
                int n = wn+nt*8+r;
                uint2 bb = *reinterpret_cast<const uint2*>(&Bsm[n*SROW+c]);
                bf[nt][0]=bb.x; bf[nt][1]=bb.y;
            }
            #pragma unroll
            for (int mt=0;mt<2;mt++)
                #pragma unroll
                for (int nt=0;nt<4;nt++){
                    asm volatile(
                      "mma.sync.aligned.m16n8k8.row.col.f32.tf32.tf32.f32 "
                      "{%0,%1,%2,%3},{%4,%5,%6,%7},{%8,%9},{%0,%1,%2,%3};"
                      : "+f"(acc[mt][nt][0]),"+f"(acc[mt][nt][1]),
                        "+f"(acc[mt][nt][2]),"+f"(acc[mt][nt][3])
                      : "r"(af[mt][0]),"r"(af[mt][1]),"r"(af[mt][2]),"r"(af[mt][3]),
                        "r"(bf[nt][0]),"r"(bf[nt][1]));
                }
        }
        int pf = kt+2;
        if (pf < KT){
            uint32_t off = (uint32_t)((pf%3)*STG64)*4u;
            cp16(dA+off, Ald+pf*16); cp16(dA+off+16, Ald+pf*16+4);
            if (bload){ cp16(dB+off, Bld+pf*16); cp16(dB+off+16, Bld+pf*16+4); }
        }
        asm volatile("cp.async.commit_group;");
    }
    #pragma unroll
    for (int mt=0;mt<2;mt++){
        int row0 = wm+mt*16+r;
        #pragma unroll
        for (int nt=0;nt<4;nt++){
            int col = bn+wn+nt*8+2*kq;
            float2 v0; v0.x = alpha*acc[mt][nt][0]; v0.y = alpha*acc[mt][nt][1];
            float2 v1; v1.x = alpha*acc[mt][nt][2]; v1.y = alpha*acc[mt][nt][3];
            *reinterpret_cast<float2*>(&Cb[(long)row0*N + col]) = v0;
            *reinterpret_cast<float2*>(&Cb[(long)(row0+8)*N + col]) = v1;
        }
    }
}

// ---- fp32 SIMT gemm with k-split (M0 = Yc*Yc^T, full fp32 accuracy) ----
#define SP 132
__global__ __launch_bounds__(256) void gemm32s_k(const float* __restrict__ A,
    const float* __restrict__ B, float* __restrict__ C,
    int N,int K,int ldA,int ldB,long bA,long bB,long bC,float alpha)
{
    __shared__ float As[8*SP], Bs[8*SP];
    int z = blockIdx.z, b = z & 31, ks = z >> 5;
    A += (long)b*bA + (long)ks*K; B += (long)b*bB + (long)ks*K; C += (long)z*bC;
    int tid = threadIdx.x;
    int rT = tid>>1, cT = (tid&1)*4;
    int m0 = (tid>>4)*8, n0 = (tid&15)*8;
    float acc[8][8];
    #pragma unroll
    for (int i=0;i<8;i++)
        #pragma unroll
        for (int j=0;j<8;j++) acc[i][j]=0.f;
    for (int k0=0;k0<K;k0+=8){
        float4 a4 = *reinterpret_cast<const float4*>(A + (long)rT*ldA + k0+cT);
        As[(cT+0)*SP+rT]=a4.x; As[(cT+1)*SP+rT]=a4.y;
        As[(cT+2)*SP+rT]=a4.z; As[(cT+3)*SP+rT]=a4.w;
        float4 b4 = *reinterpret_cast<const float4*>(B + (long)rT*ldB + k0+cT);
        Bs[(cT+0)*SP+rT]=b4.x; Bs[(cT+1)*SP+rT]=b4.y;
        Bs[(cT+2)*SP+rT]=b4.z; Bs[(cT+3)*SP+rT]=b4.w;
        __syncthreads();
        #pragma unroll
        for (int kk=0;kk<8;kk++){
            float4 a0 = *reinterpret_cast<const float4*>(&As[kk*SP+m0]);
            float4 a1 = *reinterpret_cast<const float4*>(&As[kk*SP+m0+4]);
            float4 b0 = *reinterpret_cast<const float4*>(&Bs[kk*SP+n0]);
            float4 b1 = *reinterpret_cast<const float4*>(&Bs[kk*SP+n0+4]);
            float av[8]={a0.x,a0.y,a0.z,a0.w,a1.x,a1.y,a1.z,a1.w};
            float bv[8]={b0.x,b0.y,b0.z,b0.w,b1.x,b1.y,b1.z,b1.w};
            #pragma unroll
            for (int i=0;i<8;i++)
                #pragma unroll
                for (int j=0;j<8;j++) acc[i][j] += av[i]*bv[j];
        }
        __syncthreads();
    }
    #pragma unroll
    for (int i=0;i<8;i++){
        float* cp = C + (long)(m0+i)*N + n0;
        #pragma unroll
        for (int j=0;j<8;j++) cp[j] = alpha*acc[i][j];
    }
}

__global__ void colmean_k(const float* __restrict__ x, float* __restrict__ xbar){
    int warp = blockIdx.x*8 + (threadIdx.x>>5);
    int lane = threadIdx.x&31;
    const float* p = x + (long)warp*HWD;
    float s = 0.f;
    #pragma unroll
    for (int i=0;i<32;i++) s += p[i*32 + lane];
    #pragma unroll
    for (int o=16;o>0;o>>=1) s += __shfl_down_sync(0xffffffffu, s, o);
    if (lane==0) xbar[warp] = s*(1.0f/HWD);
}

__global__ void initY_k(float* Y){
    int i = blockIdx.x*256 + threadIdx.x;
    uint32_t h = hashu((uint32_t)i*2654435761u + 12345u);
    Y[i] = (float)(h & 0xFFFFFFu)*1.1920929e-7f - 1.0f;
}

// ---- per-batch: sum 4 k-split partials of M0, Cholesky factor -> L ----
__global__ void chol_k(const float* __restrict__ P, float* __restrict__ L){
    float* Mt = dynsm;
    int b = blockIdx.x, tid = threadIdx.x;
    for (int i=tid;i<16384;i+=128){
        float v = P[(long)b*16384 + i] + P[(long)(32+b)*16384 + i]
                + P[(long)(64+b)*16384 + i] + P[(long)(96+b)*16384 + i];
        Mt[(i>>7)*129+(i&127)] = v;
    }
    __syncthreads();
    for (int j=0;j<128;j++){
        if (tid==j) Mt[j*129+j] = sqrtf(fmaxf(Mt[j*129+j], 1e-30f));
        __syncthreads();
        float lj = Mt[j*129+j];
        if (tid>j) Mt[tid*129+j] /= lj;
        __syncthreads();
        if (tid>j){
            float lij = Mt[tid*129+j];
            for (int c=j+1;c<=tid;c++) Mt[tid*129+c] -= lij*Mt[c*129+j];
        }
        __syncthreads();
    }
    float* dst = L + (long)b*16384;
    for (int i=tid;i<16384;i+=128){
        int r=i>>7, cc=i&127;
        dst[i] = (r>=cc)? Mt[r*129+cc] : 0.f;
    }
}

// ---- column-parallel forward substitution: Yout = L^{-1} Yin (per batch) ----
__global__ void trisolve_k(const float* __restrict__ L, const float* __restrict__ Yin,
                           float* __restrict__ Yout){
    float* Ls = dynsm;
    float* Ys = dynsm + 128*129;
    int b = blockIdx.y, c0 = blockIdx.x*128, tid = threadIdx.x;
    const float* Lb = L + (long)b*16384;
    const float* Yb = Yin + (long)b*PP*CCH;
    for (int i=tid;i<16384;i+=128) Ls[(i>>7)*129+(i&127)] = Lb[i];
    for (int i=tid;i<16384;i+=128) Ys[i] = Yb[(long)(i>>7)*CCH + c0 + (i&127)];
    __syncthreads();
    int c = tid;
    for (int j=0;j<128;j++){
        const float* lr = &Ls[j*129];
        float acc = 0.f;
        for (int i=0;i<j;i++) acc += lr[i]*Ys[i*128+c];
        Ys[j*128+c] = (Ys[j*128+c] - acc)/lr[j];
    }
    __syncthreads();
    float* Yo = Yout + (long)b*PP*CCH;
    for (int i=tid;i<16384;i+=128) Yo[(long)(i>>7)*CCH + c0 + (i&127)] = Ys[i];
}

// ---- per-batch: Householder tridiag of M1 + Sturm bisection top-24 ----
__global__ void eig_k(const float* __restrict__ M1, float* __restrict__ raw){
    float* A = dynsm;
    float* vv = A + 128*129;
    float* ww = vv + 128;
    float* dd = ww + 128;
    float* red = dd + 128;
    int b = blockIdx.x, tid = threadIdx.x;
    const float* src = M1 + (long)b*16384;
    for (int i=tid;i<16384;i+=128) A[(i>>7)*129+(i&127)] = src[i];
    __syncthreads();
    for (int k=0;k<126;k++){
        float xi = (tid>k)? A[tid*129+k] : 0.f;
        float nrm2 = blockSum(xi*xi, red, 4);
        float x1 = A[(k+1)*129+k];
        if (nrm2 > 1e-28f){
            float nrm = sqrtf(nrm2);
            float alpha = (x1>=0.f)? -nrm : nrm;
            float vi = xi; if (tid==k+1) vi = x1 - alpha;
            float vtv = 2.f*(nrm2 - alpha*x1);
            float tau = (vtv>1e-28f)? 2.f/vtv : 0.f;
            vv[tid] = vi; __syncthreads();
            float pi = 0.f;
            for (int j=k+1;j<128;j++) pi += A[tid*129+j]*vv[j];
            pi *= tau;
            float ptv = blockSum(pi*vi, red, 4);
            float wi = pi - 0.5f*tau*ptv*vi;
            ww[tid] = wi; __syncthreads();
            for (int j=k;j<128;j++) A[tid*129+j] -= vi*ww[j] + wi*vv[j];
            __syncthreads();
        }
    }
    dd[tid] = A[tid*129+tid];
    vv[tid] = (tid<127)? A[tid*129+tid+1] : 0.f;
    ww[tid] = vv[tid]*vv[tid];
    __syncthreads();
    if (tid < 24){
        float lo=1e30f, hi=-1e30f;
        for (int i=0;i<128;i++){
            float r = ((i>0)? fabsf(vv[i-1]) : 0.f) + fabsf(vv[i]);
            lo = fminf(lo, dd[i]-r); hi = fmaxf(hi, dd[i]+r);
        }
        int jt = 127 - tid;
        for (int it=0; it<40; it++){
            float mid = 0.5f*(lo+hi);
            int cnt = 0; float q = 1.f;
            for (int i=0;i<128;i++){
                float off = (i>0)? __fdividef(ww[i-1], q) : 0.f;
                q = dd[i] - mid - off;
                if (fabsf(q) < 1e-12f) q = -1e-12f;
                if (q < 0.f) cnt++;
            }
            if (cnt <= jt) lo = mid; else hi = mid;
        }
        float lam = 0.5f*(lo+hi);
        raw[b*24+tid] = log1pf(sqrtf(fmaxf(lam, 0.f)));
    }
}

__global__ void svdctx_k(const float* raw, const float* Ws, const float* bs,
                         const float* gs, const float* bes, float* ctx){
    __shared__ float r[24], red[8];
    int b = blockIdx.x, tid = threadIdx.x;
    if (tid<24) r[tid] = raw[b*24+tid];
    __syncthreads();
    float a = bs[tid];
    for (int k=0;k<24;k++) a += r[k]*Ws[k*256+tid];
    float m = blockSum(a, red, 8)*(1.f/256.f);
    float d = a - m;
    float v = blockSum(d*d, red, 8)*(1.f/256.f);
    ctx[b*256+tid] = geluf(d*rsqrtf(v+1e-5f)*gs[tid] + bes[tid]);
}

__global__ void embgate_k(const float* xbar, const float* W_emb, const float* ge,
                          const float* bee, const float* anchors, float* tgout){
    __shared__ float emb[256], red[8], cosv[32], sg[32];
    int b = blockIdx.x, tid = threadIdx.x;
    const float* xb = xbar + b*512;
    float a = 0.f;
    for (int c=0;c<512;c++) a += xb[c]*W_emb[c*256+tid];
    float m = blockSum(a, red, 8)*(1.f/256.f);
    float d = a - m;
    float v = blockSum(d*d, red, 8)*(1.f/256.f);
    float e = d*rsqrtf(v+1e-5f)*ge[tid] + bee[tid];
    float n2 = blockSum(e*e, red, 8);
    emb[tid] = e / fmaxf(sqrtf(n2), 1e-12f);
    __syncthreads();
    if (tid < 32){
        const float* ar = anchors + tid*256;
        float na=0.f, cs=0.f;
        for (int j=0;j<256;j++){ float av=ar[j]; na+=av*av; cs+=av*emb[j]; }
        cosv[tid] = cs / fmaxf(sqrtf(na), 1e-12f);
        sg[tid] = 0.f;
    }
    __syncthreads();
    if (tid == 0){
        int idx[3]; float val[3]; bool used[32];
        for (int i=0;i<32;i++) used[i]=false;
        for (int k=0;k<3;k++){
            int bi=0; float bv=-1e30f;
            for (int a2=0;a2<32;a2++) if (!used[a2] && cosv[a2]>bv){ bv=cosv[a2]; bi=a2; }
            used[bi]=true; idx[k]=bi; val[k]=bv;
        }
        float s=0.f, w[3];
        for (int k=0;k<3;k++){ w[k]=expf(val[k]-val[0]); s+=w[k]; }
        for (int k=0;k<3;k++) sg[idx[k]] = (1.f - cosv[idx[k]])*(w[k]/s);
    }
    __syncthreads();
    if (tid < 32) tgout[b*32+tid] = sg[tid];
}

__global__ void compart_k(const float* tg, const float* Wc1, const float* bc1,
                          const float* Wc2, const float* bc2,
                          const float* gc, const float* bec, float* pwout){
    __shared__ float t[32], h[512];
    int b = blockIdx.x, tid = threadIdx.x;
    if (tid<32) t[tid] = tg[b*32+tid];
    __syncthreads();
    for (int i=tid;i<512;i+=256){
        int c=i>>6, d=i&63;
        float a = bc1[i];
        for (int k=0;k<32;k++) a += t[k]*Wc1[c*2048 + k*64 + d];
        h[i] = geluf(a);
    }
    __syncthreads();
    int c = tid>>5;
    float a = bc2[tid];
    for (int k=0;k<64;k++) a += h[c*64+k]*Wc2[c*2048 + k*32 + (tid&31)];
    float m = a;
    #pragma unroll
    for (int o=16;o>0;o>>=1) m += __shfl_xor_sync(0xffffffffu, m, o);
    m *= (1.f/32.f);
    float d = a - m, vv = d*d;
    #pragma unroll
    for (int o=16;o>0;o>>=1) vv += __shfl_xor_sync(0xffffffffu, vv, o);
    vv *= (1.f/32.f);
    pwout[b*256+tid] = d*rsqrtf(vv+1e-5f)*gc[tid] + bec[tid];
}

__global__ void modgeo_k(const float* pw, const float* ctx, const float* geo,
                         const float* Wm, const float* bm, const float* Wg,
                         const float* bg, const float* gg, const float* beg,
                         const float* gate, float* cw, float* geoout){
    __shared__ float mi[768], red[16];
    int b = blockIdx.x, tid = threadIdx.x;
    if (tid < 256){ mi[tid]=pw[b*256+tid]; mi[256+tid]=ctx[b*256+tid]; }
    else mi[256+tid] = geo[b*256+tid-256];
    __syncthreads();
    float a = bm[tid];
    for (int k=0;k<768;k++) a += mi[k]*Wm[k*512+tid];
    cw[b*512+tid] = sigmoidf(a);
    float t = 0.f;
    if (tid < 256){
        t = bg[tid];
        for (int k=0;k<256;k++) t += mi[k]*Wg[k*256+tid];
    }
    float m = blockSum((tid<256)?t:0.f, red, 16)*(1.f/256.f);
    float d = (tid<256)? (t-m) : 0.f;
    float v = blockSum(d*d, red, 16)*(1.f/256.f);
    if (tid < 256)
        geoout[b*256+tid] = mi[512+tid] + sigmoidf(gate[tid])*(d*rsqrtf(v+1e-5f)*gg[tid] + beg[tid]);
}

__global__ void scale_k(const float* __restrict__ x, const float* __restrict__ cw,
                        float* __restrict__ out){
    long v = (long)blockIdx.x*blockDim.x + threadIdx.x;
    long base = v*4;
    float c = cw[base>>10];
    float4 xv = *reinterpret_cast<const float4*>(x+base);
    xv.x*=c; xv.y*=c; xv.z*=c; xv.w*=c;
    *reinterpret_cast<float4*>(out+base) = xv;
}

extern "C" void kernel_launch(void* const* d_in, const int* in_sizes, int n_in,
                              void* d_out, int out_size) {
    const float* x        = (const float*)d_in[0];
    const float* geo      = (const float*)d_in[1];
    const float* W_svd    = (const float*)d_in[2];
    const float* b_svd    = (const float*)d_in[3];
    const float* g_svd    = (const float*)d_in[4];
    const float* be_svd   = (const float*)d_in[5];
    const float* W_emb    = (const float*)d_in[6];
    const float* g_emb    = (const float*)d_in[7];
    const float* be_emb   = (const float*)d_in[8];
    const float* anchors  = (const float*)d_in[9];
    const float* Wc1      = (const float*)d_in[10];
    const float* bc1      = (const float*)d_in[11];
    const float* Wc2      = (const float*)d_in[12];
    const float* bc2      = (const float*)d_in[13];
    const float* gc       = (const float*)d_in[14];
    const float* bec      = (const float*)d_in[15];
    const float* W_mod    = (const float*)d_in[16];
    const float* b_mod    = (const float*)d_in[17];
    const float* geo_gate = (const float*)d_in[18];
    const float* W_geo    = (const float*)d_in[19];
    const float* b_geo    = (const float*)d_in[20];
    const float* g_geo    = (const float*)d_in[21];
    const float* be_geo   = (const float*)d_in[22];
    float* out = (float*)d_out;

    float *G,*G2,*Y,*Z,*Li,*M1,*Pb,*xbar,*raw,*ctx,*tg,*pw,*cw;
    cudaGetSymbolAddress((void**)&G,  g_G);
    cudaGetSymbolAddress((void**)&G2, g_G2);
    cudaGetSymbolAddress((void**)&Y,  g_Y);
    cudaGetSymbolAddress((void**)&Z,  g_Z);
    cudaGetSymbolAddress((void**)&Li, g_Li);
    cudaGetSymbolAddress((void**)&M1, g_M1);
    cudaGetSymbolAddress((void**)&Pb, g_P);
    cudaGetSymbolAddress((void**)&xbar, g_xbar);
    cudaGetSymbolAddress((void**)&raw, g_raw);
    cudaGetSymbolAddress((void**)&ctx, g_ctx);
    cudaGetSymbolAddress((void**)&tg,  g_tg);
    cudaGetSymbolAddress((void**)&pw,  g_pw);
    cudaGetSymbolAddress((void**)&cw,  g_cw);

    cudaFuncSetAttribute(gemmT_k, cudaFuncAttributeMaxDynamicSharedMemorySize, GT_SMEM);
    cudaFuncSetAttribute(gemmT64_k, cudaFuncAttributeMaxDynamicSharedMemorySize, GT64_SMEM);
    cudaFuncSetAttribute(mirror_k, cudaFuncAttributeMaxDynamicSharedMemorySize, 128*129*4);
    cudaFuncSetAttribute(chol_k, cudaFuncAttributeMaxDynamicSharedMemorySize, 128*129*4);
    cudaFuncSetAttribute(trisolve_k, cudaFuncAttributeMaxDynamicSharedMemorySize, (128*129+128*128)*4);
    cudaFuncSetAttribute(eig_k, cudaFuncAttributeMaxDynamicSharedMemorySize, (128*129+3*128+32)*4);

    const long bX = (long)CCH*HWD, bG = (long)CCH*CCH, bY = (long)PP*CCH, bM = (long)PP*PP;

    colmean_k<<<2048,256>>>(x, xbar);
    // Gram (symmetric): upper 10 tiles, then mirror
    gemmT_k<<<dim3(10,1,BB),256,GT_SMEM>>>(x, x, G, 512,1024, 1024,1024, bX,bX,bG, 1.0f/1024.0f, 1);
    mirror_k<<<dim3(6,1,BB),256,128*129*4>>>(G);
    // G2 = G*G (symmetric): upper 10 tiles, then mirror
    gemmT_k<<<dim3(10,1,BB),256,GT_SMEM>>>(G, G, G2, 512,512, 512,512, bG,bG,bG, 1.f, 1);
    mirror_k<<<dim3(6,1,BB),256,128*129*4>>>(G2);
    initY_k<<<BB*PP*CCH/256,256>>>(Y);

    float *Yc = Y, *Ya = Z;
    for (int t=1;t<=5;t++){
        gemmT64_k<<<dim3(8,1,BB),256,GT64_SMEM>>>(Yc, G2, Ya, 512,512, 512,512, bY,bG,bY, 1.f);
        { float* tmp=Yc; Yc=Ya; Ya=tmp; }
        if (t==3 || t==5){
            gemm32s_k<<<dim3(1,1,4*BB),256>>>(Yc, Yc, Pb, 128,128, 512,512, bY,bY,bM, 1.f);
            chol_k<<<BB,128,128*129*4>>>(Pb, Li);
            trisolve_k<<<dim3(4,BB),128,(128*129+128*128)*4>>>(Li, Yc, Ya);
            { float* tmp=Yc; Yc=Ya; Ya=tmp; }
        }
    }
    // Rayleigh-Ritz on G with orthonormal Yc
    gemmT64_k<<<dim3(8,1,BB),256,GT64_SMEM>>>(Yc, G, Ya, 512,512, 512,512, bY,bG,bY, 1.f);
    gemmT64_k<<<dim3(2,1,BB),256,GT64_SMEM>>>(Yc, Ya, M1, 128,512, 512,512, bY,bY,bM, 1.f);
    eig_k<<<BB,128,(128*129+3*128+32)*4>>>(M1, raw);

    svdctx_k<<<BB,256>>>(raw, W_svd, b_svd, g_svd, be_svd, ctx);
    embgate_k<<<BB,256>>>(xbar, W_emb, g_emb, be_emb, anchors, tg);
    compart_k<<<BB,256>>>(tg, Wc1, bc1, Wc2, bc2, gc, bec, pw);
    modgeo_k<<<BB,512>>>(pw, ctx, geo, W_mod, b_mod, W_geo, b_geo, g_geo, be_geo,
                         geo_gate, cw, out + X_ELEMS);
    scale_k<<<8192,512>>>(x, cw, out);
}

// round 15
// speedup vs baseline: 1.1555x; 1.1555x over previous
#include <cuda_runtime.h>
#include <cuda_bf16.h>
#include <math.h>
#include <stdint.h>

#define BB 32
#define CCH 512
#define HWD 1024
#define PP 128
#define X_ELEMS 16777216L

__device__ float g_G[BB*CCH*CCH];
__device__ float g_G2[BB*CCH*CCH];
__device__ float g_Y[BB*PP*CCH];
__device__ float g_Z[BB*PP*CCH];
__device__ float g_Li[BB*PP*PP];
__device__ float g_M1[BB*PP*PP];
__device__ float g_P[4*BB*PP*PP];
__device__ float g_xbar[BB*CCH];
__device__ float g_raw[BB*24];
__device__ float g_ctx[BB*256];
__device__ float g_tg[BB*32];
__device__ float g_pw[BB*256];
__device__ float g_cw[BB*CCH];

__constant__ int c_ux[10] = {0,1,2,3,1,2,3,2,3,3};
__constant__ int c_uy[10] = {0,0,0,0,1,1,1,2,2,3};
__constant__ int c_li[6]  = {1,2,3,2,3,3};
__constant__ int c_lj[6]  = {0,0,0,1,1,2};

extern __shared__ float dynsm[];

__device__ __forceinline__ float geluf(float x){
    return 0.5f*x*(1.0f + erff(x*0.70710678118654752f));
}
__device__ __forceinline__ float sigmoidf(float x){ return 1.0f/(1.0f+expf(-x)); }
__device__ __forceinline__ uint32_t hashu(uint32_t x){
    x ^= x>>16; x *= 0x7feb352dU; x ^= x>>15; x *= 0x846ca68bU; x ^= x>>16; return x;
}
__device__ __forceinline__ float blockSum(float v, float* red, int nw){
    int tid = threadIdx.x;
    #pragma unroll
    for (int o=16;o>0;o>>=1) v += __shfl_down_sync(0xffffffffu, v, o);
    if ((tid&31)==0) red[tid>>5] = v;
    __syncthreads();
    float s = 0.f;
    for (int i=0;i<nw;i++) s += red[i];
    __syncthreads();
    return s;
}

// ================= tf32 tensor-core GEMM, cp.async 3-stage pipeline =========
// C[m][n] = alpha * sum_k A[m][k]*B[n][k]; both row-major, k contiguous.
// sym=0: grid (N/128, M/128, z), z = ks*32+b.  sym=1: grid (10,1,BB) upper tiles.
#define SROW 20
#define STG  (128*SROW)
#define GT_SMEM (3*2*STG*4)

__device__ __forceinline__ void cp16(uint32_t d, const float* s){
    asm volatile("cp.async.cg.shared.global [%0], [%1], 16;" :: "r"(d), "l"(s));
}

__global__ __launch_bounds__(256,2) void gemmT_k(const float* __restrict__ A,
    const float* __restrict__ B, float* __restrict__ C,
    int N,int K,int ldA,int ldB, long bA,long bB,long bC, float alpha, int sym)
{
    uint32_t* sm = reinterpret_cast<uint32_t*>(dynsm);
    uint32_t sbase = (uint32_t)__cvta_generic_to_shared(sm);
    int z = blockIdx.z, b = z & 31, ks = z >> 5;
    int bm, bn;
    if (sym){ bm = c_uy[blockIdx.x]*128; bn = c_ux[blockIdx.x]*128; }
    else    { bm = blockIdx.y*128; bn = blockIdx.x*128; }
    const float* Ab = A + (long)b*bA + (long)bm*ldA + (long)ks*K;
    const float* Bb = B + (long)b*bB + (long)bn*ldB + (long)ks*K;
    float* Cb = C + (long)z*bC;
    int tid = threadIdx.x, lane = tid&31, wid = tid>>5;
    int lrow = tid&127, lhalf = tid>>7;
    const float* Ald = Ab + (long)lrow*ldA + lhalf*8;
    const float* Bld = Bb + (long)lrow*ldB + lhalf*8;
    uint32_t dA = sbase + (uint32_t)(lrow*SROW + lhalf*8)*4u;
    uint32_t dB = dA + STG*4;
    int wm = (wid&1)*64, wn = (wid>>1)*32;
    int r = lane>>2, kq = lane&3;
    float acc[4][4][4];
    #pragma unroll
    for (int i=0;i<4;i++)
        #pragma unroll
        for (int j=0;j<4;j++){ acc[i][j][0]=0.f; acc[i][j][1]=0.f; acc[i][j][2]=0.f; acc[i][j][3]=0.f; }

    const int KT = K>>4;
    #pragma unroll
    for (int pf=0; pf<2; pf++){
        if (pf < KT){
            uint32_t off = (uint32_t)(pf*2*STG)*4u;
            cp16(dA+off, Ald+pf*16); cp16(dA+off+16, Ald+pf*16+4);
            cp16(dB+off, Bld+pf*16); cp16(dB+off+16, Bld+pf*16+4);
        }
        asm volatile("cp.async.commit_group;");
    }
    for (int kt=0; kt<KT; kt++){
        asm volatile("cp.async.wait_group 1;");
        __syncthreads();
        int s = kt % 3;
        const uint32_t* Asm = sm + s*2*STG;
        const uint32_t* Bsm = Asm + STG;
        #pragma unroll
        for (int kh=0; kh<2; kh++){
            int ko = kh*8 + kq;
            uint32_t af[4][4], bf[4][2];
            #pragma unroll
            for (int mt=0;mt<4;mt++){
                int m = wm+mt*16+r;
                af[mt][0]=Asm[m*SROW+ko];   af[mt][1]=Asm[(m+8)*SROW+ko];
                af[mt][2]=Asm[m*SROW+ko+4]; af[mt][3]=Asm[(m+8)*SROW+ko+4];
            }
            #pragma unroll
            for (int nt=0;nt<4;nt++){
                int n = wn+nt*8+r;
                bf[nt][0]=Bsm[n*SROW+ko]; bf[nt][1]=Bsm[n*SROW+ko+4];
            }
            #pragma unroll
            for (int mt=0;mt<4;mt++)
                #pragma unroll
                for (int nt=0;nt<4;nt++){
                    asm volatile(
                      "mma.sync.aligned.m16n8k8.row.col.f32.tf32.tf32.f32 "
                      "{%0,%1,%2,%3},{%4,%5,%6,%7},{%8,%9},{%0,%1,%2,%3};"
                      : "+f"(acc[mt][nt][0]),"+f"(acc[mt][nt][1]),
                        "+f"(acc[mt][nt][2]),"+f"(acc[mt][nt][3])
                      : "r"(af[mt][0]),"r"(af[mt][1]),"r"(af[mt][2]),"r"(af[mt][3]),
                        "r"(bf[nt][0]),"r"(bf[nt][1]));
                }
        }
        int pf = kt+2;
        if (pf < KT){
            uint32_t off = (uint32_t)((pf%3)*2*STG)*4u;
            cp16(dA+off, Ald+pf*16); cp16(dA+off+16, Ald+pf*16+4);
            cp16(dB+off, Bld+pf*16); cp16(dB+off+16, Bld+pf*16+4);
        }
        asm volatile("cp.async.commit_group;");
    }
    #pragma unroll
    for (int mt=0;mt<4;mt++){
        int row0 = bm+wm+mt*16+r;
        #pragma unroll
        for (int nt=0;nt<4;nt++){
            int col = bn+wn+nt*8+2*kq;
            float2 v0; v0.x = alpha*acc[mt][nt][0]; v0.y = alpha*acc[mt][nt][1];
            float2 v1; v1.x = alpha*acc[mt][nt][2]; v1.y = alpha*acc[mt][nt][3];
            *reinterpret_cast<float2*>(&Cb[(long)row0*N + col]) = v0;
            *reinterpret_cast<float2*>(&Cb[(long)(row0+8)*N + col]) = v1;
        }
    }
}

// ---- mirror lower tiles from upper tiles (symmetric 512x512 per batch) ----
__global__ void mirror_k(float* __restrict__ G){
    float* s = dynsm;   // 128*129
    int ti = c_li[blockIdx.x], tj = c_lj[blockIdx.x];
    int b = blockIdx.z, tid = threadIdx.x;
    float* Gb = G + (long)b*CCH*CCH;
    const float* src = Gb + (long)(tj*128)*CCH + ti*128;
    float* dst = Gb + (long)(ti*128)*CCH + tj*128;
    for (int idx=tid; idx<16384; idx+=256){
        int r=idx>>7, c=idx&127;
        s[r*129+c] = src[(long)r*CCH + c];
    }
    __syncthreads();
    for (int idx=tid; idx<16384; idx+=256){
        int r=idx>>7, c=idx&127;
        dst[(long)r*CCH + c] = s[c*129+r];
    }
}

// ========== 128x64-tile tf32 GEMM (M fixed = 128): fills the chip ==========
#define ASTG (128*SROW)
#define BSTG (64*SROW)
#define STG64 (ASTG+BSTG)
#define GT64_SMEM (3*STG64*4)

__global__ __launch_bounds__(256,2) void gemmT64_k(const float* __restrict__ A,
    const float* __restrict__ B, float* __restrict__ C,
    int N,int K,int ldA,int ldB, long bA,long bB,long bC, float alpha)
{
    uint32_t* sm = reinterpret_cast<uint32_t*>(dynsm);
    uint32_t sbase = (uint32_t)__cvta_generic_to_shared(sm);
    int b = blockIdx.z;
    int bn = blockIdx.x*64;
    const float* Ab = A + (long)b*bA;
    const float* Bb = B + (long)b*bB + (long)bn*ldB;
    float* Cb = C + (long)b*bC;
    int tid = threadIdx.x, lane = tid&31, wid = tid>>5;
    int lrow = tid&127, lhalf = tid>>7;
    const float* Ald = Ab + (long)lrow*ldA + lhalf*8;
    uint32_t dA = sbase + (uint32_t)(lrow*SROW + lhalf*8)*4u;
    int brow = tid&63, bhalf = (tid>>6)&1;
    const float* Bld = Bb + (long)brow*ldB + bhalf*8;
    uint32_t dB = sbase + (uint32_t)(ASTG + brow*SROW + bhalf*8)*4u;
    bool bload = (tid < 128);
    int wm = (wid&3)*32, wn = (wid>>2)*32;
    int r = lane>>2, kq = lane&3;
    float acc[2][4][4];
    #pragma unroll
    for (int i=0;i<2;i++)
        #pragma unroll
        for (int j=0;j<4;j++){ acc[i][j][0]=0.f; acc[i][j][1]=0.f; acc[i][j][2]=0.f; acc[i][j][3]=0.f; }

    const int KT = K>>4;
    #pragma unroll
    for (int pf=0; pf<2; pf++){
        if (pf < KT){
            uint32_t off = (uint32_t)(pf*STG64)*4u;
            cp16(dA+off, Ald+pf*16); cp16(dA+off+16, Ald+pf*16+4);
            if (bload){ cp16(dB+off, Bld+pf*16); cp16(dB+off+16, Bld+pf*16+4); }
        }
        asm volatile("cp.async.commit_group;");
    }
    for (int kt=0; kt<KT; kt++){
        asm volatile("cp.async.wait_group 1;");
        __syncthreads();
        const uint32_t* Asm = sm + (kt%3)*STG64;
        const uint32_t* Bsm = Asm + ASTG;
        #pragma unroll
        for (int kh=0; kh<2; kh++){
            int ko = kh*8 + kq;
            uint32_t af[2][4], bf[4][2];
            #pragma unroll
            for (int mt=0;mt<2;mt++){
                int m = wm+mt*16+r;
                af[mt][0]=Asm[m*SROW+ko];   af[mt][1]=Asm[(m+8)*SROW+ko];
                af[mt][2]=Asm[m*SROW+ko+4]; af[mt][3]=Asm[(m+8)*SROW+ko+4];
            }
            #pragma unroll
            for (int nt=0;nt<4;nt++){
                int n = wn+nt*8+r;
                bf[nt][0]=Bsm[n*SROW+ko]; bf[nt][1]=Bsm[n*SROW+ko+4];
            }
            #pragma unroll
            for (int mt=0;mt<2;mt++)
                #pragma unroll
                for (int nt=0;nt<4;nt++){
                    asm volatile(
                      "mma.sync.aligned.m16n8k8.row.col.f32.tf32.tf32.f32 "
                      "{%0,%1,%2,%3},{%4,%5,%6,%7},{%8,%9},{%0,%1,%2,%3};"
                      : "+f"(acc[mt][nt][0]),"+f"(acc[mt][nt][1]),
                        "+f"(acc[mt][nt][2]),"+f"(acc[mt][nt][3])
                      : "r"(af[mt][0]),"r"(af[mt][1]),"r"(af[mt][2]),"r"(af[mt][3]),
                        "r"(bf[nt][0]),"r"(bf[nt][1]));
                }
        }
        int pf = kt+2;
        if (pf < KT){
            uint32_t off = (uint32_t)((pf%3)*STG64)*4u;
            cp16(dA+off, Ald+pf*16); cp16(dA+off+16, Ald+pf*16+4);
            if (bload){ cp16(dB+off, Bld+pf*16); cp16(dB+off+16, Bld+pf*16+4); }
        }
        asm volatile("cp.async.commit_group;");
    }
    #pragma unroll
    for (int mt=0;mt<2;mt++){
        int row0 = wm+mt*16+r;
        #pragma unroll
        for (int nt=0;nt<4;nt++){
            int col = bn+wn+nt*8+2*kq;
            float2 v0; v0.x = alpha*acc[mt][nt][0]; v0.y = alpha*acc[mt][nt][1];
            float2 v1; v1.x = alpha*acc[mt][nt][2]; v1.y = alpha*acc[mt][nt][3];
            *reinterpret_cast<float2*>(&Cb[(long)row0*N + col]) = v0;
            *reinterpret_cast<float2*>(&Cb[(long)(row0+8)*N + col]) = v1;
        }
    }
}

// ---- fp32 SIMT gemm with k-split (M0 = Yc*Yc^T, full fp32 accuracy) ----
#define SP 132
__global__ __launch_bounds__(256) void gemm32s_k(const float* __restrict__ A,
    const float* __restrict__ B, float* __restrict__ C,
    int N,int K,int ldA,int ldB,long bA,long bB,long bC,float alpha)
{
    __shared__ float As[8*SP], Bs[8*SP];
    int z = blockIdx.z, b = z & 31, ks = z >> 5;
    A += (long)b*bA + (long)ks*K; B += (long)b*bB + (long)ks*K; C += (long)z*bC;
    int tid = threadIdx.x;
    int rT = tid>>1, cT = (tid&1)*4;
    int m0 = (tid>>4)*8, n0 = (tid&15)*8;
    float acc[8][8];
    #pragma unroll
    for (int i=0;i<8;i++)
        #pragma unroll
        for (int j=0;j<8;j++) acc[i][j]=0.f;
    for (int k0=0;k0<K;k0+=8){
        float4 a4 = *reinterpret_cast<const float4*>(A + (long)rT*ldA + k0+cT);
        As[(cT+0)*SP+rT]=a4.x; As[(cT+1)*SP+rT]=a4.y;
        As[(cT+2)*SP+rT]=a4.z; As[(cT+3)*SP+rT]=a4.w;
        float4 b4 = *reinterpret_cast<const float4*>(B + (long)rT*ldB + k0+cT);
        Bs[(cT+0)*SP+rT]=b4.x; Bs[(cT+1)*SP+rT]=b4.y;
        Bs[(cT+2)*SP+rT]=b4.z; Bs[(cT+3)*SP+rT]=b4.w;
        __syncthreads();
        #pragma unroll
        for (int kk=0;kk<8;kk++){
            float4 a0 = *reinterpret_cast<const float4*>(&As[kk*SP+m0]);
            float4 a1 = *reinterpret_cast<const float4*>(&As[kk*SP+m0+4]);
            float4 b0 = *reinterpret_cast<const float4*>(&Bs[kk*SP+n0]);
            float4 b1 = *reinterpret_cast<const float4*>(&Bs[kk*SP+n0+4]);
            float av[8]={a0.x,a0.y,a0.z,a0.w,a1.x,a1.y,a1.z,a1.w};
            float bv[8]={b0.x,b0.y,b0.z,b0.w,b1.x,b1.y,b1.z,b1.w};
            #pragma unroll
            for (int i=0;i<8;i++)
                #pragma unroll
                for (int j=0;j<8;j++) acc[i][j] += av[i]*bv[j];
        }
        __syncthreads();
    }
    #pragma unroll
    for (int i=0;i<8;i++){
        float* cp = C + (long)(m0+i)*N + n0;
        #pragma unroll
        for (int j=0;j<8;j++) cp[j] = alpha*acc[i][j];
    }
}

__global__ void colmean_k(const float* __restrict__ x, float* __restrict__ xbar){
    int warp = blockIdx.x*8 + (threadIdx.x>>5);
    int lane = threadIdx.x&31;
    const float* p = x + (long)warp*HWD;
    float s = 0.f;
    #pragma unroll
    for (int i=0;i<32;i++) s += p[i*32 + lane];
    #pragma unroll
    for (int o=16;o>0;o>>=1) s += __shfl_down_sync(0xffffffffu, s, o);
    if (lane==0) xbar[warp] = s*(1.0f/HWD);
}

__global__ void initY_k(float* Y){
    int i = blockIdx.x*256 + threadIdx.x;
    uint32_t h = hashu((uint32_t)i*2654435761u + 12345u);
    Y[i] = (float)(h & 0xFFFFFFu)*1.1920929e-7f - 1.0f;
}

// ---- per-batch: sum 4 k-split partials of M0, Cholesky factor -> L (256 thr) ----
__global__ void chol_k(const float* __restrict__ P, float* __restrict__ L){
    float* Mt = dynsm;
    int b = blockIdx.x, tid = threadIdx.x;
    int row = tid & 127, half = tid >> 7;
    for (int i=tid;i<16384;i+=256){
        float v = P[(long)b*16384 + i] + P[(long)(32+b)*16384 + i]
                + P[(long)(64+b)*16384 + i] + P[(long)(96+b)*16384 + i];
        Mt[(i>>7)*129+(i&127)] = v;
    }
    __syncthreads();
    for (int j=0;j<128;j++){
        if (tid==j) Mt[j*129+j] = sqrtf(fmaxf(Mt[j*129+j], 1e-30f));
        __syncthreads();
        float lj = Mt[j*129+j];
        if (half==0 && row>j) Mt[row*129+j] /= lj;
        __syncthreads();
        if (row>j){
            float lij = Mt[row*129+j];
            for (int c=j+1+half; c<=row; c+=2) Mt[row*129+c] -= lij*Mt[c*129+j];
        }
        __syncthreads();
    }
    float* dst = L + (long)b*16384;
    for (int i=tid;i<16384;i+=256){
        int r=i>>7, cc=i&127;
        dst[i] = (r>=cc)? Mt[r*129+cc] : 0.f;
    }
}

// ---- column-parallel forward substitution: Yout = L^{-1} Yin (per batch) ----
__global__ void trisolve_k(const float* __restrict__ L, const float* __restrict__ Yin,
                           float* __restrict__ Yout){
    float* Ls = dynsm;
    float* Ys = dynsm + 128*129;
    int b = blockIdx.y, c0 = blockIdx.x*128, tid = threadIdx.x;
    const float* Lb = L + (long)b*16384;
    const float* Yb = Yin + (long)b*PP*CCH;
    for (int i=tid;i<16384;i+=128) Ls[(i>>7)*129+(i&127)] = Lb[i];
    for (int i=tid;i<16384;i+=128) Ys[i] = Yb[(long)(i>>7)*CCH + c0 + (i&127)];
    __syncthreads();
    int c = tid;
    for (int j=0;j<128;j++){
        const float* lr = &Ls[j*129];
        float acc = 0.f;
        for (int i=0;i<j;i++) acc += lr[i]*Ys[i*128+c];
        Ys[j*128+c] = (Ys[j*128+c] - acc)/lr[j];
    }
    __syncthreads();
    float* Yo = Yout + (long)b*PP*CCH;
    for (int i=tid;i<16384;i+=128) Yo[(long)(i>>7)*CCH + c0 + (i&127)] = Ys[i];
}

// ---- per-batch (256 thr): Householder tridiag of M1 + Sturm bisection top-24 ----
#define EIG_SMEM ((16512 + 384 + 256 + 32)*4)
__global__ void eig_k(const float* __restrict__ M1, float* __restrict__ raw){
    float* A = dynsm;            // 128*129
    float* vv = A + 16512;
    float* ww = vv + 128;
    float* dd = ww + 128;
    float* p2 = dd + 128;        // 256
    float* red = p2 + 256;       // 32
    int b = blockIdx.x, tid = threadIdx.x;
    int row = tid & 127, half = tid >> 7;
    const float* src = M1 + (long)b*16384;
    for (int i=tid;i<16384;i+=256) A[(i>>7)*129+(i&127)] = src[i];
    __syncthreads();
    for (int k=0;k<126;k++){
        float xi = (half==0 && row>k)? A[row*129+k] : 0.f;
        float nrm2 = blockSum(xi*xi, red, 8);
        float x1 = A[(k+1)*129+k];
        if (nrm2 > 1e-28f){
            float nrm = sqrtf(nrm2);
            float alpha = (x1>=0.f)? -nrm : nrm;
            float vtv = 2.f*(nrm2 - alpha*x1);
            float tau = (vtv>1e-28f)? 2.f/vtv : 0.f;
            if (half==0){
                float vi = xi; if (row==k+1) vi = x1 - alpha;
                vv[row] = vi;
            }
            __syncthreads();
            float partial = 0.f;
            for (int j=k+1+half; j<128; j+=2) partial += A[row*129+j]*vv[j];
            p2[half*128+row] = partial;
            __syncthreads();
            float vr = vv[row];
            float pi = (p2[row] + p2[128+row]) * tau;
            float ptv = blockSum((half==0)? pi*vr : 0.f, red, 8);
            if (half==0) ww[row] = pi - 0.5f*tau*ptv*vr;
            __syncthreads();
            float wr = ww[row];
            for (int j=k+half; j<128; j+=2) A[row*129+j] -= vr*ww[j] + wr*vv[j];
            __syncthreads();
        }
    }
    if (half==0){
        dd[row] = A[row*129+row];
        vv[row] = (row<127)? A[row*129+row+1] : 0.f;
        ww[row] = vv[row]*vv[row];
    }
    __syncthreads();
    if (tid < 24){
        float lo=1e30f, hi=-1e30f;
        for (int i=0;i<128;i++){
            float r = ((i>0)? fabsf(vv[i-1]) : 0.f) + fabsf(vv[i]);
            lo = fminf(lo, dd[i]-r); hi = fmaxf(hi, dd[i]+r);
        }
        int jt = 127 - tid;
        for (int it=0; it<40; it++){
            float mid = 0.5f*(lo+hi);
            int cnt = 0; float q = 1.f;
            for (int i=0;i<128;i++){
                float off = (i>0)? __fdividef(ww[i-1], q) : 0.f;
                q = dd[i] - mid - off;
                if (fabsf(q) < 1e-12f) q = -1e-12f;
                if (q < 0.f) cnt++;
            }
            if (cnt <= jt) lo = mid; else hi = mid;
        }
        float lam = 0.5f*(lo+hi);
        raw[b*24+tid] = log1pf(sqrtf(fmaxf(lam, 0.f)));
    }
}

__global__ void svdctx_k(const float* raw, const float* Ws, const float* bs,
                         const float* gs, const float* bes, float* ctx){
    __shared__ float r[24], red[8];
    int b = blockIdx.x, tid = threadIdx.x;
    if (tid<24) r[tid] = raw[b*24+tid];
    __syncthreads();
    float a = bs[tid];
    for (int k=0;k<24;k++) a += r[k]*Ws[k*256+tid];
    float m = blockSum(a, red, 8)*(1.f/256.f);
    float d = a - m;
    float v = blockSum(d*d, red, 8)*(1.f/256.f);
    ctx[b*256+tid] = geluf(d*rsqrtf(v+1e-5f)*gs[tid] + bes[tid]);
}

__global__ void embgate_k(const float* xbar, const float* W_emb, const float* ge,
                          const float* bee, const float* anchors, float* tgout){
    __shared__ float emb[256], red[8], cosv[32], sg[32];
    int b = blockIdx.x, tid = threadIdx.x;
    const float* xb = xbar + b*512;
    float a = 0.f;
    for (int c=0;c<512;c++) a += xb[c]*W_emb[c*256+tid];
    float m = blockSum(a, red, 8)*(1.f/256.f);
    float d = a - m;
    float v = blockSum(d*d, red, 8)*(1.f/256.f);
    float e = d*rsqrtf(v+1e-5f)*ge[tid] + bee[tid];
    float n2 = blockSum(e*e, red, 8);
    emb[tid] = e / fmaxf(sqrtf(n2), 1e-12f);
    __syncthreads();
    if (tid < 32){
        const float* ar = anchors + tid*256;
        float na=0.f, cs=0.f;
        for (int j=0;j<256;j++){ float av=ar[j]; na+=av*av; cs+=av*emb[j]; }
        cosv[tid] = cs / fmaxf(sqrtf(na), 1e-12f);
        sg[tid] = 0.f;
    }
    __syncthreads();
    if (tid == 0){
        int idx[3]; float val[3]; bool used[32];
        for (int i=0;i<32;i++) used[i]=false;
        for (int k=0;k<3;k++){
            int bi=0; float bv=-1e30f;
            for (int a2=0;a2<32;a2++) if (!used[a2] && cosv[a2]>bv){ bv=cosv[a2]; bi=a2; }
            used[bi]=true; idx[k]=bi; val[k]=bv;
        }
        float s=0.f, w[3];
        for (int k=0;k<3;k++){ w[k]=expf(val[k]-val[0]); s+=w[k]; }
        for (int k=0;k<3;k++) sg[idx[k]] = (1.f - cosv[idx[k]])*(w[k]/s);
    }
    __syncthreads();
    if (tid < 32) tgout[b*32+tid] = sg[tid];
}

__global__ void compart_k(const float* tg, const float* Wc1, const float* bc1,
                          const float* Wc2, const float* bc2,
                          const float* gc, const float* bec, float* pwout){
    __shared__ float t[32], h[512];
    int b = blockIdx.x, tid = threadIdx.x;
    if (tid<32) t[tid] = tg[b*32+tid];
    __syncthreads();
    for (int i=tid;i<512;i+=256){
        int c=i>>6, d=i&63;
        float a = bc1[i];
        for (int k=0;k<32;k++) a += t[k]*Wc1[c*2048 + k*64 + d];
        h[i] = geluf(a);
    }
    __syncthreads();
    int c = tid>>5;
    float a = bc2[tid];
    for (int k=0;k<64;k++) a += h[c*64+k]*Wc2[c*2048 + k*32 + (tid&31)];
    float m = a;
    #pragma unroll
    for (int o=16;o>0;o>>=1) m += __shfl_xor_sync(0xffffffffu, m, o);
    m *= (1.f/32.f);
    float d = a - m, vv = d*d;
    #pragma unroll
    for (int o=16;o>0;o>>=1) vv += __shfl_xor_sync(0xffffffffu, vv, o);
    vv *= (1.f/32.f);
    pwout[b*256+tid] = d*rsqrtf(vv+1e-5f)*gc[tid] + bec[tid];
}

__global__ void modgeo_k(const float* pw, const float* ctx, const float* geo,
                         const float* Wm, const float* bm, const float* Wg,
                         const float* bg, const float* gg, const float* beg,
                         const float* gate, float* cw, float* geoout){
    __shared__ float mi[768], red[16];
    int b = blockIdx.x, tid = threadIdx.x;
    if (tid < 256){ mi[tid]=pw[b*256+tid]; mi[256+tid]=ctx[b*256+tid]; }
    else mi[256+tid] = geo[b*256+tid-256];
    __syncthreads();
    float a = bm[tid];
    for (int k=0;k<768;k++) a += mi[k]*Wm[k*512+tid];
    cw[b*512+tid] = sigmoidf(a);
    float t = 0.f;
    if (tid < 256){
        t = bg[tid];
        for (int k=0;k<256;k++) t += mi[k]*Wg[k*256+tid];
    }
    float m = blockSum((tid<256)?t:0.f, red, 16)*(1.f/256.f);
    float d = (tid<256)? (t-m) : 0.f;
    float v = blockSum(d*d, red, 16)*(1.f/256.f);
    if (tid < 256)
        geoout[b*256+tid] = mi[512+tid] + sigmoidf(gate[tid])*(d*rsqrtf(v+1e-5f)*gg[tid] + beg[tid]);
}

__global__ void scale_k(const float* __restrict__ x, const float* __restrict__ cw,
                        float* __restrict__ out){
    long v = (long)blockIdx.x*blockDim.x + threadIdx.x;
    long base = v*4;
    float c = cw[base>>10];
    float4 xv = *reinterpret_cast<const float4*>(x+base);
    xv.x*=c; xv.y*=c; xv.z*=c; xv.w*=c;
    *reinterpret_cast<float4*>(out+base) = xv;
}

extern "C" void kernel_launch(void* const* d_in, const int* in_sizes, int n_in,
                              void* d_out, int out_size) {
    const float* x        = (const float*)d_in[0];
    const float* geo      = (const float*)d_in[1];
    const float* W_svd    = (const float*)d_in[2];
    const float* b_svd    = (const float*)d_in[3];
    const float* g_svd    = (const float*)d_in[4];
    const float* be_svd   = (const float*)d_in[5];
    const float* W_emb    = (const float*)d_in[6];
    const float* g_emb    = (const float*)d_in[7];
    const float* be_emb   = (const float*)d_in[8];
    const float* anchors  = (const float*)d_in[9];
    const float* Wc1      = (const float*)d_in[10];
    const float* bc1      = (const float*)d_in[11];
    const float* Wc2      = (const float*)d_in[12];
    const float* bc2      = (const float*)d_in[13];
    const float* gc       = (const float*)d_in[14];
    const float* bec      = (const float*)d_in[15];
    const float* W_mod    = (const float*)d_in[16];
    const float* b_mod    = (const float*)d_in[17];
    const float* geo_gate = (const float*)d_in[18];
    const float* W_geo    = (const float*)d_in[19];
    const float* b_geo    = (const float*)d_in[20];
    const float* g_geo    = (const float*)d_in[21];
    const float* be_geo   = (const float*)d_in[22];
    float* out = (float*)d_out;

    float *G,*G2,*Y,*Z,*Li,*M1,*Pb,*xbar,*raw,*ctx,*tg,*pw,*cw;
    cudaGetSymbolAddress((void**)&G,  g_G);
    cudaGetSymbolAddress((void**)&G2, g_G2);
    cudaGetSymbolAddress((void**)&Y,  g_Y);
    cudaGetSymbolAddress((void**)&Z,  g_Z);
    cudaGetSymbolAddress((void**)&Li, g_Li);
    cudaGetSymbolAddress((void**)&M1, g_M1);
    cudaGetSymbolAddress((void**)&Pb, g_P);
    cudaGetSymbolAddress((void**)&xbar, g_xbar);
    cudaGetSymbolAddress((void**)&raw, g_raw);
    cudaGetSymbolAddress((void**)&ctx, g_ctx);
    cudaGetSymbolAddress((void**)&tg,  g_tg);
    cudaGetSymbolAddress((void**)&pw,  g_pw);
    cudaGetSymbolAddress((void**)&cw,  g_cw);

    cudaFuncSetAttribute(gemmT_k, cudaFuncAttributeMaxDynamicSharedMemorySize, GT_SMEM);
    cudaFuncSetAttribute(gemmT64_k, cudaFuncAttributeMaxDynamicSharedMemorySize, GT64_SMEM);
    cudaFuncSetAttribute(mirror_k, cudaFuncAttributeMaxDynamicSharedMemorySize, 128*129*4);
    cudaFuncSetAttribute(chol_k, cudaFuncAttributeMaxDynamicSharedMemorySize, 128*129*4);
    cudaFuncSetAttribute(trisolve_k, cudaFuncAttributeMaxDynamicSharedMemorySize, (128*129+128*128)*4);
    cudaFuncSetAttribute(eig_k, cudaFuncAttributeMaxDynamicSharedMemorySize, EIG_SMEM);

    const long bX = (long)CCH*HWD, bG = (long)CCH*CCH, bY = (long)PP*CCH, bM = (long)PP*PP;

    colmean_k<<<2048,256>>>(x, xbar);
    // Gram (symmetric): upper 10 tiles, then mirror
    gemmT_k<<<dim3(10,1,BB),256,GT_SMEM>>>(x, x, G, 512,1024, 1024,1024, bX,bX,bG, 1.0f/1024.0f, 1);
    mirror_k<<<dim3(6,1,BB),256,128*129*4>>>(G);
    // G2 = G*G (symmetric): upper 10 tiles, then mirror
    gemmT_k<<<dim3(10,1,BB),256,GT_SMEM>>>(G, G, G2, 512,512, 512,512, bG,bG,bG, 1.f, 1);
    mirror_k<<<dim3(6,1,BB),256,128*129*4>>>(G2);
    initY_k<<<BB*PP*CCH/256,256>>>(Y);

    float *Yc = Y, *Ya = Z;
    for (int t=1;t<=5;t++){
        gemmT64_k<<<dim3(8,1,BB),256,GT64_SMEM>>>(Yc, G2, Ya, 512,512, 512,512, bY,bG,bY, 1.f);
        { float* tmp=Yc; Yc=Ya; Ya=tmp; }
        if (t==3 || t==5){
            gemm32s_k<<<dim3(1,1,4*BB),256>>>(Yc, Yc, Pb, 128,128, 512,512, bY,bY,bM, 1.f);
            chol_k<<<BB,256,128*129*4>>>(Pb, Li);
            trisolve_k<<<dim3(4,BB),128,(128*129+128*128)*4>>>(Li, Yc, Ya);
            { float* tmp=Yc; Yc=Ya; Ya=tmp; }
        }
    }
    // Rayleigh-Ritz on G with orthonormal Yc
    gemmT64_k<<<dim3(8,1,BB),256,GT64_SMEM>>>(Yc, G, Ya, 512,512, 512,512, bY,bG,bY, 1.f);
    gemmT64_k<<<dim3(2,1,BB),256,GT64_SMEM>>>(Yc, Ya, M1, 128,512, 512,512, bY,bY,bM, 1.f);
    eig_k<<<BB,256,EIG_SMEM>>>(M1, raw);

    svdctx_k<<<BB,256>>>(raw, W_svd, b_svd, g_svd, be_svd, ctx);
    embgate_k<<<BB,256>>>(xbar, W_emb, g_emb, be_emb, anchors, tg);
    compart_k<<<BB,256>>>(tg, Wc1, bc1, Wc2, bc2, gc, bec, pw);
    modgeo_k<<<BB,512>>>(pw, ctx, geo, W_mod, b_mod, W_geo, b_geo, g_geo, be_geo,
                         geo_gate, cw, out + X_ELEMS);
    scale_k<<<8192,512>>>(x, cw, out);
}